// round 4
// baseline (speedup 1.0000x reference)
#include <cuda_runtime.h>
#include <cstdint>

#define ORD   24
#define TLEN  168
#define DD    512
#define SS    336
#define BB    256
#define ROWF2 26          // float2 slots per coef row: 24 coefs + bias + pad (208B)
#define T_CHUNKS 4
#define TCH   (TLEN / T_CHUNKS)      // 42
#define NTILE (BB * T_CHUNKS)        // 1024 tiles (tile = batch x T-chunk)
#define GRIDB (148 * 3)              // 444 persistent CTAs (3/SM @ 85 regs, 35KB smem)

// Scratch (no cudaMalloc allowed).
__device__ float2 g_coef[TLEN * ROWF2];
__device__ int g_counter = 0;   // work-stealing counter (self-resets per launch)
__device__ int g_done    = 0;

// ---------------------------------------------------------------------------
// Packed fp32x2 helpers (sm_103a). PTX-only; ptxas won't auto-fuse.
// ---------------------------------------------------------------------------
__device__ __forceinline__ unsigned long long fma2(unsigned long long a,
                                                   unsigned long long x,
                                                   unsigned long long c) {
    unsigned long long d;
    asm("fma.rn.f32x2 %0, %1, %2, %3;" : "=l"(d) : "l"(a), "l"(x), "l"(c));
    return d;
}
__device__ __forceinline__ unsigned long long add2(unsigned long long a,
                                                   unsigned long long b) {
    unsigned long long d;
    asm("add.rn.f32x2 %0, %1, %2;" : "=l"(d) : "l"(a), "l"(b));
    return d;
}

// ---------------------------------------------------------------------------
// Kernel A: build coefficient table. Thread j owns the coefficient of ctx_j
// through the 168-step recurrence (j==24 accumulates the bias column).
// ---------------------------------------------------------------------------
__global__ void ar_coef_kernel(const float* __restrict__ W,
                               const float* __restrict__ b) {
    const int j = threadIdx.x;
    if (j > 24) return;

    float w[ORD];
#pragma unroll
    for (int i = 0; i < ORD; i++) w[i] = W[i];
    const float bias = b[0];

    float m[ORD];
#pragma unroll
    for (int i = 0; i < ORD; i++) m[i] = (j < ORD && i == j) ? 1.0f : 0.0f;

    for (int t = 0; t < TLEN; t++) {
        float p[ORD];
#pragma unroll
        for (int i = 0; i < ORD; i++) p[i] = w[i] * m[i];
#pragma unroll
        for (int k = 0; k < 12; k++) p[k] = p[2 * k] + p[2 * k + 1];
#pragma unroll
        for (int k = 0; k < 6; k++)  p[k] = p[2 * k] + p[2 * k + 1];
#pragma unroll
        for (int k = 0; k < 3; k++)  p[k] = p[2 * k] + p[2 * k + 1];
        float y = (p[0] + p[1]) + p[2];
        if (j == 24) y += bias;

        g_coef[t * ROWF2 + j] = make_float2(y, y);  // duplicated for f32x2

#pragma unroll
        for (int i = 0; i < ORD - 1; i++) m[i] = m[i + 1];
        m[ORD - 1] = y;
    }
    // PDL: table is complete; let the dependent kernel pass its sync point.
    cudaTriggerProgrammaticLaunchCompletion();
}

// ---------------------------------------------------------------------------
// Kernel B: persistent work-stealing tiles. tile = (chunk, batch).
// 256 threads = the 256 d-pairs of one batch. Each thread:
//   out[b, t, d:d+2] = C[t] . ctx[b, :, d:d+2] + beta[t]  for 42 t's.
// ctx = 24 packed f32x2 regs; coef rows broadcast from smem (hoistable now).
// ---------------------------------------------------------------------------
__global__ void __launch_bounds__(256, 3)
ar_main_kernel(const float* __restrict__ x, float* __restrict__ out) {
    __shared__ float2 sc[TLEN * ROWF2];   // full 34.9 KB coef table
    __shared__ int s_tile;

    const int tid = threadIdx.x;
    int tile = blockIdx.x;                // first tile without the atomic

    // Prefetch first tile's ctx BEFORE the PDL sync (x is independent of A).
    unsigned long long ctx[ORD];
    {
        const int batch = tile & (BB - 1);
        const float* xp = x + ((size_t)batch * SS + (SS - ORD)) * DD + tid * 2;
#pragma unroll
        for (int jj = 0; jj < ORD; jj++)
            ctx[jj] = *reinterpret_cast<const unsigned long long*>(
                xp + (size_t)jj * DD);
    }

    // Wait until kernel A's coefficient table is visible.
    cudaGridDependencySynchronize();

    // Cooperative load of the coef table (float4 granularity, 2184 vec4s).
    {
        const float4* gsrc = reinterpret_cast<const float4*>(g_coef);
        float4* sdst = reinterpret_cast<float4*>(sc);
        for (int i = tid; i < TLEN * ROWF2 / 2; i += 256) sdst[i] = gsrc[i];
    }
    __syncthreads();

    for (;;) {
        const int batch = tile & (BB - 1);
        const int t0    = (tile >> 8) * TCH;

        float* op = out + (size_t)batch * TLEN * DD + (size_t)t0 * DD + tid * 2;

        for (int tt = 0; tt < TCH; tt++) {
            const ulonglong2* row =
                reinterpret_cast<const ulonglong2*>(sc + (t0 + tt) * ROWF2);
            const unsigned long long bias =
                *reinterpret_cast<const unsigned long long*>(
                    sc + (t0 + tt) * ROWF2 + 24);

            unsigned long long a0 = bias, a1 = 0ull;
#pragma unroll
            for (int jj = 0; jj < ORD; jj += 2) {
                ulonglong2 c2 = row[jj >> 1];   // coefs jj, jj+1, each {c,c}
                a0 = fma2(c2.x, ctx[jj],     a0);
                a1 = fma2(c2.y, ctx[jj + 1], a1);
            }
            union { unsigned long long u; float2 f; } r;
            r.u = add2(a0, a1);
            __stcs(reinterpret_cast<float2*>(op + (size_t)tt * DD), r.f);
        }

        // Grab next tile.
        __syncthreads();
        if (tid == 0) s_tile = GRIDB + atomicAdd(&g_counter, 1);
        __syncthreads();
        tile = s_tile;
        if (tile >= NTILE) break;

        // Load next tile's ctx.
        const int nb = tile & (BB - 1);
        const float* xp = x + ((size_t)nb * SS + (SS - ORD)) * DD + tid * 2;
#pragma unroll
        for (int jj = 0; jj < ORD; jj++)
            ctx[jj] = *reinterpret_cast<const unsigned long long*>(
                xp + (size_t)jj * DD);
    }

    // Self-reset counters so each graph replay is identical.
    if (tid == 0) {
        const int d = atomicAdd(&g_done, 1);
        if (d == GRIDB - 1) {
            atomicExch(&g_counter, 0);
            atomicExch(&g_done, 0);
        }
    }
}

// ---------------------------------------------------------------------------
extern "C" void kernel_launch(void* const* d_in, const int* in_sizes, int n_in,
                              void* d_out, int out_size) {
    const float* x = (const float*)d_in[0];   // [256, 336, 512] f32
    const float* W = (const float*)d_in[1];   // [24, 1] f32
    const float* b = (const float*)d_in[2];   // [1] f32
    float* out = (float*)d_out;               // [256, 168, 512] f32

    ar_coef_kernel<<<1, 32>>>(W, b);

    // Programmatic dependent launch: B starts while A runs, overlapping B's
    // launch latency + first ctx loads with A's serial recurrence.
    cudaLaunchConfig_t cfg = {};
    cfg.gridDim = dim3(GRIDB, 1, 1);
    cfg.blockDim = dim3(256, 1, 1);
    cfg.dynamicSmemBytes = 0;
    cfg.stream = 0;
    cudaLaunchAttribute attrs[1];
    attrs[0].id = cudaLaunchAttributeProgrammaticStreamSerialization;
    attrs[0].val.programmaticStreamSerializationAllowed = 1;
    cfg.attrs = attrs;
    cfg.numAttrs = 1;
    cudaLaunchKernelEx(&cfg, ar_main_kernel, x, out);
}

// round 5
// speedup vs baseline: 1.3563x; 1.3563x over previous
#include <cuda_runtime.h>
#include <cstdint>

#define ORD   24
#define TLEN  168
#define DD    512
#define SS    336
#define BB    256
#define CROW  28            // padded coef row stride in floats (112B, 16B-aligned)
#define DQW   128           // d-quarter width handled per tile
#define NTILE (BB * 4)      // 1024 tiles = batch x d-quarter
#define GRIDB 296           // 148 SMs x 2 resident CTAs, single wave

__device__ int g_counter = 0;   // work-stealing counter (self-resets per launch)
__device__ int g_done    = 0;

// ---------------------------------------------------------------------------
// Packed fp32x2 helpers (sm_103a). PTX-only; ptxas won't auto-fuse.
// ---------------------------------------------------------------------------
__device__ __forceinline__ unsigned long long fma2(unsigned long long a,
                                                   unsigned long long x,
                                                   unsigned long long c) {
    unsigned long long d;
    asm("fma.rn.f32x2 %0, %1, %2, %3;" : "=l"(d) : "l"(a), "l"(x), "l"(c));
    return d;
}
__device__ __forceinline__ unsigned long long dup2(float c) {
    unsigned long long d;
    asm("mov.b64 %0, {%1, %1};" : "=l"(d) : "f"(c));
    return d;
}

// ---------------------------------------------------------------------------
// Fused kernel: per-CTA coef prologue + register-blocked GEMM mainloop.
//   Tile = (batch, d-quarter).  CTA: 256 threads = 8 warps.
//   Warp w covers t in [21w, 21w+21) as 3 passes of Mt=7.
//   Lane l covers d-group l (4 floats) within the 128-wide quarter.
//   Thread register tile: 7t x 4d accumulated as packed f32x2.
// ---------------------------------------------------------------------------
__global__ void __launch_bounds__(256, 2)
ar_fused_kernel(const float* __restrict__ x, const float* __restrict__ W,
                const float* __restrict__ bptr, float* __restrict__ out) {
    __shared__ __align__(16) float scoef[TLEN * CROW];  // 18.8 KB coef table
    __shared__ __align__(16) float sctx[ORD * DQW];     // 12 KB ctx tile
    __shared__ int s_tile;

    const int tid  = threadIdx.x;
    const int warp = tid >> 5;
    const int lane = tid & 31;

    int tile = blockIdx.x;   // first tile pre-assigned (GRIDB < NTILE)

    // ---- stage ctx for the first tile (all threads) ----
    {
        const int batch = tile >> 2, dq = tile & 3;
        const float* xb =
            x + ((size_t)batch * SS + (SS - ORD)) * DD + dq * DQW;
        for (int v = tid; v < ORD * DQW / 4; v += 256) {
            const int j = v >> 5, c = v & 31;   // DQW/4 == 32 float4 per row
            reinterpret_cast<float4*>(sctx)[v] =
                reinterpret_cast<const float4*>(xb + (size_t)j * DD)[c];
        }
    }

    // ---- coef prologue: thread j owns coefficient column j (j==24: bias) ----
    if (tid < 25) {
        const int j = tid;
        float w[ORD];
#pragma unroll
        for (int i = 0; i < ORD; i++) w[i] = W[i];
        const float bias = bptr[0];

        float m[ORD];
#pragma unroll
        for (int i = 0; i < ORD; i++) m[i] = (j < ORD && i == j) ? 1.0f : 0.0f;

        for (int t = 0; t < TLEN; t++) {
            float p[ORD];
#pragma unroll
            for (int i = 0; i < ORD; i++) p[i] = w[i] * m[i];
#pragma unroll
            for (int k = 0; k < 12; k++) p[k] = p[2 * k] + p[2 * k + 1];
#pragma unroll
            for (int k = 0; k < 6; k++)  p[k] = p[2 * k] + p[2 * k + 1];
#pragma unroll
            for (int k = 0; k < 3; k++)  p[k] = p[2 * k] + p[2 * k + 1];
            float y = (p[0] + p[1]) + p[2];
            if (j == 24) y += bias;

            scoef[t * CROW + j] = y;

#pragma unroll
            for (int i = 0; i < ORD - 1; i++) m[i] = m[i + 1];
            m[ORD - 1] = y;
        }
    }
    __syncthreads();

    // ---- persistent mainloop ----
    for (;;) {
        const int batch = tile >> 2, dq = tile & 3;
        float* ob = out + (size_t)batch * TLEN * DD + dq * DQW + lane * 4;

#pragma unroll 1
        for (int p = 0; p < 3; p++) {
            const int t0 = warp * 21 + p * 7;

            ulonglong2 acc[7];
#pragma unroll
            for (int i = 0; i < 7; i++) {
                const unsigned long long bb =
                    dup2(scoef[(t0 + i) * CROW + 24]);
                acc[i].x = bb;
                acc[i].y = bb;
            }

#pragma unroll
            for (int kb = 0; kb < 6; kb++) {
                // ctx fragment: 4 k-rows x 4 d (warp-wide LDS.128)
                const int koff = kb * 4;
                const ulonglong2 b0 = *reinterpret_cast<const ulonglong2*>(
                    &sctx[(koff + 0) * DQW + lane * 4]);
                const ulonglong2 b1 = *reinterpret_cast<const ulonglong2*>(
                    &sctx[(koff + 1) * DQW + lane * 4]);
                const ulonglong2 b2 = *reinterpret_cast<const ulonglong2*>(
                    &sctx[(koff + 2) * DQW + lane * 4]);
                const ulonglong2 b3 = *reinterpret_cast<const ulonglong2*>(
                    &sctx[(koff + 3) * DQW + lane * 4]);

#pragma unroll
                for (int i = 0; i < 7; i++) {
                    // coef fragment: 4 k for this t (broadcast LDS.128)
                    const float4 af = *reinterpret_cast<const float4*>(
                        &scoef[(t0 + i) * CROW + koff]);
                    unsigned long long c;
                    c = dup2(af.x);
                    acc[i].x = fma2(c, b0.x, acc[i].x);
                    acc[i].y = fma2(c, b0.y, acc[i].y);
                    c = dup2(af.y);
                    acc[i].x = fma2(c, b1.x, acc[i].x);
                    acc[i].y = fma2(c, b1.y, acc[i].y);
                    c = dup2(af.z);
                    acc[i].x = fma2(c, b2.x, acc[i].x);
                    acc[i].y = fma2(c, b2.y, acc[i].y);
                    c = dup2(af.w);
                    acc[i].x = fma2(c, b3.x, acc[i].x);
                    acc[i].y = fma2(c, b3.y, acc[i].y);
                }
            }

#pragma unroll
            for (int i = 0; i < 7; i++) {
                union { ulonglong2 u; float4 f; } r;
                r.u = acc[i];
                __stcs(reinterpret_cast<float4*>(ob + (size_t)(t0 + i) * DD),
                       r.f);
            }
        }

        // ---- steal next tile ----
        __syncthreads();   // everyone done reading sctx
        if (tid == 0) s_tile = GRIDB + atomicAdd(&g_counter, 1);
        __syncthreads();
        tile = s_tile;
        if (tile >= NTILE) break;

        {   // stage ctx for the next tile
            const int nb = tile >> 2, ndq = tile & 3;
            const float* xb =
                x + ((size_t)nb * SS + (SS - ORD)) * DD + ndq * DQW;
            for (int v = tid; v < ORD * DQW / 4; v += 256) {
                const int j = v >> 5, c = v & 31;
                reinterpret_cast<float4*>(sctx)[v] =
                    reinterpret_cast<const float4*>(xb + (size_t)j * DD)[c];
            }
        }
        __syncthreads();
    }

    // ---- self-reset counters so each graph replay is identical ----
    if (tid == 0) {
        const int d = atomicAdd(&g_done, 1);
        if (d == GRIDB - 1) {
            atomicExch(&g_counter, 0);
            atomicExch(&g_done, 0);
        }
    }
}

// ---------------------------------------------------------------------------
extern "C" void kernel_launch(void* const* d_in, const int* in_sizes, int n_in,
                              void* d_out, int out_size) {
    const float* x = (const float*)d_in[0];   // [256, 336, 512] f32
    const float* W = (const float*)d_in[1];   // [24, 1] f32
    const float* b = (const float*)d_in[2];   // [1] f32
    float* out = (float*)d_out;               // [256, 168, 512] f32

    ar_fused_kernel<<<GRIDB, 256>>>(x, W, b, out);
}